// round 8
// baseline (speedup 1.0000x reference)
#include <cuda_runtime.h>
#include <cuda_bf16.h>
#include <cstdint>
#include <cstddef>

#define NMAX 50000
#define EMAX 800000
#define DF   128
#define NC   64

// ---------------- scratch (static device globals; no allocation) -------------
__device__ float g_dinv[NMAX];
__device__ float g_buf[(size_t)NMAX * DF];
__device__ int   g_cnt[NMAX];
__device__ int   g_off[NMAX + 1];
__device__ int   g_cur[NMAX];
__device__ int   g_csr[EMAX];
__device__ int   g_idx64;
// decoupled-lookback scan state (reset by k_count each replay)
__device__ int            g_blkagg[64];
__device__ int            g_blkpre[64];
__device__ volatile int   g_blkst[64];
// W^T split to bf16 hi/lo, padded layout [n*136 + k] halves: [layer][hi/lo]
__device__ __align__(16) unsigned char g_wt[3][2][128 * 272];

// ---------------- edge utils ---------------------------------------------------
__device__ __forceinline__ int edge_at(const void* e, long long i, int is64) {
    return is64 ? (int)((const long long*)e)[i] : ((const int*)e)[i];
}

// ------- fused: zero counts + detect dtype + W prep (independent ranges) -------
__global__ void k_init_prepw(const void* edges,
                             const float* __restrict__ W1,
                             const float* __restrict__ W2,
                             const float* __restrict__ W3, int n) {
    int i = blockIdx.x * blockDim.x + threadIdx.x;
    if (i < n) g_cnt[i] = 0;
    if (i == 0) {
        const long long* p = (const long long*)edges;
        int ok = 1;
        #pragma unroll
        for (int j = 0; j < 16; j++) {
            long long v = p[j];
            if (v < 0 || v >= NMAX) ok = 0;
        }
        g_idx64 = ok;
    }
    if (i < 16384 * 2 + 8192) {
        int layer, nout, e;
        const float* W;
        if (i < 16384)      { layer = 0; nout = 128; e = i;         W = W1; }
        else if (i < 32768) { layer = 1; nout = 128; e = i - 16384; W = W2; }
        else                { layer = 2; nout = 64;  e = i - 32768; W = W3; }
        int k = e / nout, nn = e % nout;
        float w = W[k * nout + nn];
        __nv_bfloat16 hi = __float2bfloat16(w);
        __nv_bfloat16 lo = __float2bfloat16(w - __bfloat162float(hi));
        uint32_t off = (uint32_t)(nn * 136 + k) * 2;
        *(__nv_bfloat16*)&g_wt[layer][0][off] = hi;
        *(__nv_bfloat16*)&g_wt[layer][1][off] = lo;
    }
}

// ------- count in-degrees; also reset lookback flags for the next kernel -------
__global__ void k_count(const void* __restrict__ edges, long long E) {
    long long i = (long long)blockIdx.x * blockDim.x + threadIdx.x;
    if (blockIdx.x == 0 && threadIdx.x < 64) {
        g_blkst[threadIdx.x] = 0;       // clean flags every replay
    }
    if (i < E) atomicAdd(&g_cnt[edge_at(edges, E + i, g_idx64)], 1);
}

// ------- single-kernel exclusive scan (decoupled lookback, 49 blocks) ----------
__global__ void __launch_bounds__(1024) k_scanlb(int n, int E) {
    __shared__ int sm[1024];
    __shared__ int s_base;
    const int t = threadIdx.x;
    const int bid = blockIdx.x;
    const int i = bid * 1024 + t;
    const int v = (i < n) ? g_cnt[i] : 0;
    sm[t] = v;
    __syncthreads();
    #pragma unroll
    for (int o = 1; o < 1024; o <<= 1) {
        int u = (t >= o) ? sm[t - o] : 0;
        __syncthreads();
        sm[t] += u;
        __syncthreads();
    }
    if (t == 0) {
        int agg = sm[1023];
        if (bid == 0) {
            g_blkpre[0] = agg;
            __threadfence();
            g_blkst[0] = 2;
            s_base = 0;
        } else {
            g_blkagg[bid] = agg;
            __threadfence();
            g_blkst[bid] = 1;
            int ex = 0;
            for (int p = bid - 1; p >= 0; ) {
                int st;
                while ((st = g_blkst[p]) == 0) { }
                if (st == 2) { ex += g_blkpre[p]; break; }
                ex += g_blkagg[p];
                p--;
            }
            g_blkpre[bid] = ex + agg;
            __threadfence();
            g_blkst[bid] = 2;
            s_base = ex;
        }
    }
    __syncthreads();
    if (i < n) {
        int incl = sm[t] + s_base;
        int off = incl - v;
        g_off[i] = off;
        g_cur[i] = off;
        g_dinv[i] = rsqrtf((float)(v + 1));   // +1 self loop
        if (i == n - 1) g_off[n] = E;
    }
}

__global__ void k_fill(const void* __restrict__ edges, long long E) {
    long long i = (long long)blockIdx.x * blockDim.x + threadIdx.x;
    if (i < E) {
        int is64 = g_idx64;
        int s = edge_at(edges, i, is64);
        int d = edge_at(edges, E + i, is64);
        g_csr[atomicAdd(&g_cur[d], 1)] = s;
    }
}

// ------------- HMMA GEMM: g_buf[r] = dinv[r] * (X @ W)[r] ----------------------
__device__ __forceinline__ void lm_x4(uint32_t& r0, uint32_t& r1, uint32_t& r2,
                                      uint32_t& r3, uint32_t a) {
    asm volatile("ldmatrix.sync.aligned.m8n8.x4.shared.b16 {%0,%1,%2,%3}, [%4];"
                 : "=r"(r0), "=r"(r1), "=r"(r2), "=r"(r3) : "r"(a));
}
__device__ __forceinline__ void lm_x2(uint32_t& r0, uint32_t& r1, uint32_t a) {
    asm volatile("ldmatrix.sync.aligned.m8n8.x2.shared.b16 {%0,%1}, [%2];"
                 : "=r"(r0), "=r"(r1) : "r"(a));
}
__device__ __forceinline__ void mma_bf16(float* c, uint32_t a0, uint32_t a1,
                                         uint32_t a2, uint32_t a3,
                                         uint32_t b0, uint32_t b1) {
    asm volatile("mma.sync.aligned.m16n8k16.row.col.f32.bf16.bf16.f32 "
                 "{%0,%1,%2,%3}, {%4,%5,%6,%7}, {%8,%9}, {%0,%1,%2,%3};"
                 : "+f"(c[0]), "+f"(c[1]), "+f"(c[2]), "+f"(c[3])
                 : "r"(a0), "r"(a1), "r"(a2), "r"(a3), "r"(b0), "r"(b1));
}

template<int NOUT, bool RELU>
__global__ void __launch_bounds__(256) k_hgemm(const float* __restrict__ X,
                                               int layer, int n) {
    extern __shared__ char sm[];
    constexpr int BSZ = NOUT * 272;
    constexpr int B_HI = 0;
    constexpr int B_LO = BSZ;
    constexpr int A_HI = 2 * BSZ;
    constexpr int A_LO = 2 * BSZ + 128 * 272;
    const int t = threadIdx.x;
    const int row0 = blockIdx.x * 128;

    uint32_t sb;
    asm("{ .reg .u64 u; cvta.to.shared.u64 u, %1; cvt.u32.u64 %0, u; }"
        : "=r"(sb) : "l"(sm));

    {
        const float4* s0 = (const float4*)&g_wt[layer][0][0];
        const float4* s1 = (const float4*)&g_wt[layer][1][0];
        float4* d0 = (float4*)(sm + B_HI);
        float4* d1 = (float4*)(sm + B_LO);
        #pragma unroll
        for (int i = t; i < BSZ / 16; i += 256) { d0[i] = s0[i]; d1[i] = s1[i]; }
    }

    {
        const int row = t >> 1;
        const int c0 = (t & 1) * 64;
        const int gr = row0 + row;
        const float4* xr = (const float4*)(X + (size_t)gr * 128 + c0);
        char* ah = sm + A_HI + row * 272 + c0 * 2;
        char* al = sm + A_LO + row * 272 + c0 * 2;
        #pragma unroll 4
        for (int q = 0; q < 16; q++) {
            float4 v = (gr < n) ? xr[q] : make_float4(0.f, 0.f, 0.f, 0.f);
            if (RELU) {
                v.x = fmaxf(v.x, 0.f); v.y = fmaxf(v.y, 0.f);
                v.z = fmaxf(v.z, 0.f); v.w = fmaxf(v.w, 0.f);
            }
            __nv_bfloat162 h0, h1, l0, l1;
            h0.x = __float2bfloat16(v.x); h0.y = __float2bfloat16(v.y);
            h1.x = __float2bfloat16(v.z); h1.y = __float2bfloat16(v.w);
            l0.x = __float2bfloat16(v.x - __bfloat162float(h0.x));
            l0.y = __float2bfloat16(v.y - __bfloat162float(h0.y));
            l1.x = __float2bfloat16(v.z - __bfloat162float(h1.x));
            l1.y = __float2bfloat16(v.w - __bfloat162float(h1.y));
            *(__nv_bfloat162*)(ah + q * 8)     = h0;
            *(__nv_bfloat162*)(ah + q * 8 + 4) = h1;
            *(__nv_bfloat162*)(al + q * 8)     = l0;
            *(__nv_bfloat162*)(al + q * 8 + 4) = l1;
        }
    }
    __syncthreads();

    const int warp = t >> 5, lane = t & 31;
    constexpr int NCH = NOUT / 8;
    float acc[NCH][4];
    #pragma unroll
    for (int nc = 0; nc < NCH; nc++)
        #pragma unroll
        for (int q = 0; q < 4; q++) acc[nc][q] = 0.f;

    const uint32_t aRow = sb + A_HI
        + (uint32_t)(warp * 16 + (lane & 7) + ((lane >> 3) & 1) * 8) * 272
        + (lane >> 4) * 16;
    const int bl = lane & 15;
    const uint32_t bRow = sb + B_HI + (uint32_t)(bl & 7) * 272 + ((bl >> 3) & 1) * 16;

    #pragma unroll
    for (int kc = 0; kc < 8; kc++) {
        uint32_t ah0, ah1, ah2, ah3, al0, al1, al2, al3;
        lm_x4(ah0, ah1, ah2, ah3, aRow + kc * 32);
        lm_x4(al0, al1, al2, al3, aRow + kc * 32 + (A_LO - A_HI));
        #pragma unroll
        for (int nc = 0; nc < NCH; nc++) {
            uint32_t bh0, bh1, bl0, bl1;
            uint32_t ba = bRow + (uint32_t)nc * 8 * 272 + kc * 32;
            lm_x2(bh0, bh1, ba);
            lm_x2(bl0, bl1, ba + BSZ);
            mma_bf16(acc[nc], ah0, ah1, ah2, ah3, bh0, bh1);
            mma_bf16(acc[nc], ah0, ah1, ah2, ah3, bl0, bl1);
            mma_bf16(acc[nc], al0, al1, al2, al3, bh0, bh1);
        }
    }

    {
        const int r0 = row0 + warp * 16 + (lane >> 2);
        const int r1 = r0 + 8;
        const int cb = (lane & 3) * 2;
        const float dv0 = (r0 < n) ? g_dinv[r0] : 0.f;
        const float dv1 = (r1 < n) ? g_dinv[r1] : 0.f;
        #pragma unroll
        for (int nc = 0; nc < NCH; nc++) {
            int col = nc * 8 + cb;
            if (r0 < n) {
                float2 o; o.x = dv0 * acc[nc][0]; o.y = dv0 * acc[nc][1];
                *(float2*)(g_buf + (size_t)r0 * NOUT + col) = o;
            }
            if (r1 < n) {
                float2 o; o.x = dv1 * acc[nc][2]; o.y = dv1 * acc[nc][3];
                *(float2*)(g_buf + (size_t)r1 * NOUT + col) = o;
            }
        }
    }
}

// ---------------- CSR gather: e[d] = dd*(self + sum_s buf[s]) + b --------------
__global__ void k_gather128(const float* __restrict__ bias,
                            float* __restrict__ e, int n) {
    int w = (blockIdx.x * blockDim.x + threadIdx.x) >> 5;
    int lane = threadIdx.x & 31;
    if (w >= n) return;
    int j = g_off[w], end = g_off[w + 1];
    float dd = g_dinv[w];
    float4 a0 = *(const float4*)(g_buf + (size_t)w * 128 + lane * 4);
    float4 a1 = make_float4(0.f, 0.f, 0.f, 0.f);
    float4 a2 = make_float4(0.f, 0.f, 0.f, 0.f);
    float4 a3 = make_float4(0.f, 0.f, 0.f, 0.f);
    for (; j + 4 <= end; j += 4) {
        int s0 = __ldg(&g_csr[j]);
        int s1 = __ldg(&g_csr[j + 1]);
        int s2 = __ldg(&g_csr[j + 2]);
        int s3 = __ldg(&g_csr[j + 3]);
        float4 v0 = *(const float4*)(g_buf + (size_t)s0 * 128 + lane * 4);
        float4 v1 = *(const float4*)(g_buf + (size_t)s1 * 128 + lane * 4);
        float4 v2 = *(const float4*)(g_buf + (size_t)s2 * 128 + lane * 4);
        float4 v3 = *(const float4*)(g_buf + (size_t)s3 * 128 + lane * 4);
        a0.x += v0.x; a0.y += v0.y; a0.z += v0.z; a0.w += v0.w;
        a1.x += v1.x; a1.y += v1.y; a1.z += v1.z; a1.w += v1.w;
        a2.x += v2.x; a2.y += v2.y; a2.z += v2.z; a2.w += v2.w;
        a3.x += v3.x; a3.y += v3.y; a3.z += v3.z; a3.w += v3.w;
    }
    for (; j < end; j++) {
        int s0 = __ldg(&g_csr[j]);
        float4 v0 = *(const float4*)(g_buf + (size_t)s0 * 128 + lane * 4);
        a0.x += v0.x; a0.y += v0.y; a0.z += v0.z; a0.w += v0.w;
    }
    a0.x += a1.x + a2.x + a3.x;
    a0.y += a1.y + a2.y + a3.y;
    a0.z += a1.z + a2.z + a3.z;
    a0.w += a1.w + a2.w + a3.w;
    float4 bb = *(const float4*)(bias + lane * 4);
    float4 o;
    o.x = fmaf(dd, a0.x, bb.x); o.y = fmaf(dd, a0.y, bb.y);
    o.z = fmaf(dd, a0.z, bb.z); o.w = fmaf(dd, a0.w, bb.w);
    *(float4*)(e + (size_t)w * 128 + lane * 4) = o;
}

__global__ void k_gather64_lsm(const float* __restrict__ bias,
                               float* __restrict__ e3,
                               float* __restrict__ logp, int n) {
    int w = (blockIdx.x * blockDim.x + threadIdx.x) >> 5;
    int lane = threadIdx.x & 31;
    if (w >= n) return;
    int j = g_off[w], end = g_off[w + 1];
    float dd = g_dinv[w];
    float2 a0 = *(const float2*)(g_buf + (size_t)w * 64 + lane * 2);
    float2 a1 = make_float2(0.f, 0.f);
    float2 a2 = make_float2(0.f, 0.f);
    float2 a3 = make_float2(0.f, 0.f);
    for (; j + 4 <= end; j += 4) {
        int s0 = __ldg(&g_csr[j]);
        int s1 = __ldg(&g_csr[j + 1]);
        int s2 = __ldg(&g_csr[j + 2]);
        int s3 = __ldg(&g_csr[j + 3]);
        float2 v0 = *(const float2*)(g_buf + (size_t)s0 * 64 + lane * 2);
        float2 v1 = *(const float2*)(g_buf + (size_t)s1 * 64 + lane * 2);
        float2 v2 = *(const float2*)(g_buf + (size_t)s2 * 64 + lane * 2);
        float2 v3 = *(const float2*)(g_buf + (size_t)s3 * 64 + lane * 2);
        a0.x += v0.x; a0.y += v0.y;
        a1.x += v1.x; a1.y += v1.y;
        a2.x += v2.x; a2.y += v2.y;
        a3.x += v3.x; a3.y += v3.y;
    }
    for (; j < end; j++) {
        int s0 = __ldg(&g_csr[j]);
        float2 v0 = *(const float2*)(g_buf + (size_t)s0 * 64 + lane * 2);
        a0.x += v0.x; a0.y += v0.y;
    }
    a0.x += a1.x + a2.x + a3.x;
    a0.y += a1.y + a2.y + a3.y;
    float2 bb = *(const float2*)(bias + lane * 2);
    float r0 = fmaf(dd, a0.x, bb.x);
    float r1 = fmaf(dd, a0.y, bb.y);
    float2 ev; ev.x = r0; ev.y = r1;
    *(float2*)(e3 + (size_t)w * 64 + lane * 2) = ev;
    float mx = fmaxf(r0, r1);
    #pragma unroll
    for (int o = 16; o; o >>= 1) mx = fmaxf(mx, __shfl_xor_sync(0xffffffffu, mx, o));
    float sum = expf(r0 - mx) + expf(r1 - mx);
    #pragma unroll
    for (int o = 16; o; o >>= 1) sum += __shfl_xor_sync(0xffffffffu, sum, o);
    float lz = mx + logf(sum);
    float2 lp; lp.x = r0 - lz; lp.y = r1 - lz;
    *(float2*)(logp + (size_t)w * 64 + lane * 2) = lp;
}

// ---------------- launcher ------------------------------------------------------
extern "C" void kernel_launch(void* const* d_in, const int* in_sizes, int n_in,
                              void* d_out, int out_size) {
    const float* x  = (const float*)d_in[0];
    const void*  ed = d_in[1];
    const float* W1 = (const float*)d_in[2];
    const float* b1 = (const float*)d_in[3];
    const float* W2 = (const float*)d_in[4];
    const float* b2 = (const float*)d_in[5];
    const float* W3 = (const float*)d_in[6];
    const float* b3 = (const float*)d_in[7];

    int       N = in_sizes[0] / DF;
    long long E = (long long)in_sizes[1] / 2;

    float* out  = (float*)d_out;
    float* logp = out;
    float* e1   = out + (size_t)N * NC;
    float* e2   = e1 + (size_t)N * DF;
    float* e3   = e2 + (size_t)N * DF;

    const int smem128 = 2 * 128 * 272 + 2 * 128 * 272;
    const int smem64  = 2 * 64 * 272 + 2 * 128 * 272;
    cudaFuncSetAttribute((const void*)k_hgemm<128, false>,
                         cudaFuncAttributeMaxDynamicSharedMemorySize, smem128);
    cudaFuncSetAttribute((const void*)k_hgemm<128, true>,
                         cudaFuncAttributeMaxDynamicSharedMemorySize, smem128);
    cudaFuncSetAttribute((const void*)k_hgemm<64, true>,
                         cudaFuncAttributeMaxDynamicSharedMemorySize, smem64);

    int nb_init  = (N > 16384 * 2 + 8192 ? N : 16384 * 2 + 8192);
    nb_init = (nb_init + 255) / 256;
    int nb_edges = (int)((E + 255) / 256);
    int nb_scan  = (N + 1023) / 1024;
    int nb_gemm  = (N + 127) / 128;
    int nb_gat   = (N + 7) / 8;

    // ---- CSR build + W prep (4 kernels) ----
    k_init_prepw<<<nb_init, 256>>>(ed, W1, W2, W3, N);
    k_count<<<nb_edges, 256>>>(ed, E);
    k_scanlb<<<nb_scan, 1024>>>(N, (int)E);
    k_fill<<<nb_edges, 256>>>(ed, E);

    // ---- layer 1 ----
    k_hgemm<128, false><<<nb_gemm, 256, smem128>>>(x, 0, N);
    k_gather128<<<nb_gat, 256>>>(b1, e1, N);

    // ---- layer 2 (relu fused into A conversion) ----
    k_hgemm<128, true><<<nb_gemm, 256, smem128>>>(e1, 1, N);
    k_gather128<<<nb_gat, 256>>>(b2, e2, N);

    // ---- layer 3 + fused log_softmax ----
    k_hgemm<64, true><<<nb_gemm, 256, smem64>>>(e2, 2, N);
    k_gather64_lsm<<<nb_gat, 256>>>(b3, e3, logp, N);
}